// round 13
// baseline (speedup 1.0000x reference)
#include <cuda_runtime.h>

#define BB   512
#define TM1  99
#define NF   128
#define HH   256
#define WOFF (BB*TM1*NF)
#define NBLK 128
#define NTHR 512
#define NGRP 8                 // 8 independent groups of 16 CTAs

typedef unsigned long long ull;

// ---------------- device scratch ----------------
__device__ float  g_z2T[(size_t)BB*TM1*NF]; // transposed: [b][s][n]
__device__ float  g_h[2][BB*HH];
__device__ float  g_c[2][BB*HH];
__device__ float4 g_Wt4[384*256];         // [k][j] -> (Wi,Wf,Wg,Wo)
__device__ ull    g_W1T2[256*128];        // [kp][s] -> (W1[s][2kp], W1[s][2kp+1]), s pad 128
__device__ float  g_bias[1024];

// barrier state: each counter/release on its own 128B line; monotonic epochs,
// never reset (base epoch re-read at each kernel start)
struct __align__(128) PadU { unsigned v; unsigned pad[31]; };
__device__ PadU g_cnt[NGRP];
__device__ PadU g_rel[NGRP];
__device__ PadU g_cntG;
__device__ PadU g_relG;

// ---------------- math helpers ----------------
__device__ __forceinline__ float ex2f(float x){ float y; asm("ex2.approx.f32 %0, %1;" : "=f"(y) : "f"(x)); return y; }
__device__ __forceinline__ float rcpf(float x){ float y; asm("rcp.approx.f32 %0, %1;" : "=f"(y) : "f"(x)); return y; }
__device__ __forceinline__ float tanha(float x){ float y; asm("tanh.approx.f32 %0, %1;" : "=f"(y) : "f"(x)); return y; }
__device__ __forceinline__ float tanh_f(float x){
    float a  = fabsf(x);
    float em = ex2f(a * -2.8853900817779268f);
    float r  = (1.0f - em) * rcpf(1.0f + em);
    return copysignf(r, x);
}
__device__ __forceinline__ float sigm_f(float x){
    float e = ex2f(x * -1.4426950408889634f);
    return rcpf(1.0f + e);
}
__device__ __forceinline__ float wsum(float v){
    #pragma unroll
    for (int o = 16; o; o >>= 1) v += __shfl_xor_sync(0xffffffffu, v, o);
    return v;
}
__device__ __forceinline__ float wmax(float v){
    #pragma unroll
    for (int o = 16; o; o >>= 1) v = fmaxf(v, __shfl_xor_sync(0xffffffffu, v, o));
    return v;
}
__device__ __forceinline__ ull pack2(float a, float b){ ull r; asm("mov.b64 %0, {%1,%2};" : "=l"(r) : "f"(a), "f"(b)); return r; }
__device__ __forceinline__ float2 unpack2(ull v){ float2 r; asm("mov.b64 {%0,%1}, %2;" : "=f"(r.x), "=f"(r.y) : "l"(v)); return r; }
#define FFMA2(d,a,b) asm("fma.rn.f32x2 %0, %1, %2, %0;" : "+l"(d) : "l"(a), "l"(b))

// ---------------- group-local barrier (16 CTAs per group) ----------------
__device__ __forceinline__ void groupbar(int g, unsigned e){
    __threadfence();                         // release
    __syncthreads();
    if (threadIdx.x == 0) {
        unsigned old = atomicAdd(&g_cnt[g].v, 1u);
        if ((old & 15u) == 15u) {
            *((volatile unsigned*)&g_rel[g].v) = e;
        } else {
            while (*((volatile unsigned*)&g_rel[g].v) < e) { }
        }
        __threadfence();                     // acquire + drop stale L1 lines
    }
    __syncthreads();
}

// ---------------- global barrier (all 128 CTAs), one-time ----------------
__device__ __forceinline__ void globalbar(){
    __threadfence();
    __syncthreads();
    if (threadIdx.x == 0) {
        unsigned base = *((volatile unsigned*)&g_relG.v);  // safe: no release until we arrive
        unsigned old  = atomicAdd(&g_cntG.v, 1u);
        if ((old & 127u) == 127u) {
            *((volatile unsigned*)&g_relG.v) = base + 1u;
        } else {
            while (*((volatile unsigned*)&g_relG.v) < base + 1u) { }
        }
        __threadfence();
    }
    __syncthreads();
}

// ---------------- single persistent kernel ----------------
// grid = 128 x 512. block = (grp = bid>>4, u = bid&15).
// attention: batches grp*64+u*4..+4.  LSTM: j-tile u, batches grp*64..+64.
// dyn smem (floats): wsmu 24576 | xsf 24832 | hc 2048 | z1s 512 | es 512 | w3s 128 | b1s 128
#define SMEM_PERSIST (52736*4)
__global__ __launch_bounds__(NTHR, 1) void persist_kernel(
    const float* __restrict__ in,
    const float* __restrict__ W1,   const float* __restrict__ b1,
    const float* __restrict__ W2,   const float* __restrict__ b2,
    const float* __restrict__ W3,   const float* __restrict__ b3,
    const float* __restrict__ W_ih, const float* __restrict__ W_hh,
    const float* __restrict__ b_ih, const float* __restrict__ b_hh,
    float* __restrict__ out)
{
    extern __shared__ float sm[];
    ull*   wsmu = (ull*)sm;                  // [gate][kp][q] (98304 B)
    float* xsf  = sm + 24576;                // [bb][k], row stride 388 floats
    float* hc   = sm + 49408;                // 4*512
    float* z1s  = sm + 51456;                // 4*128
    float* es   = sm + 51968;                // 4*128
    float* w3s  = sm + 52480;                // 128
    float* b1s  = sm + 52608;                // 128

    int bid = blockIdx.x, tid = threadIdx.x;
    int wrp = tid >> 5, l = tid & 31;
    int grp = bid >> 4, u = bid & 15;
    int jt  = u, bt = grp;
    int b0  = grp*64 + u*4;                  // attention batches

    // group epoch base (stable until this block's first arrival)
    unsigned bar = *((volatile unsigned*)&g_rel[grp].v);

    // ================= PREP PHASE (grid-strided) =================
    {
        int gtid = bid*NTHR + tid;
        int gstride = NBLK*NTHR;
        for (int idx = gtid; idx < 384*256; idx += gstride) {
            int k = idx >> 8, j = idx & 255;
            float4 v;
            if (k < 128) {
                v.x = W_ih[(j      )*128 + k];
                v.y = W_ih[(j + 256)*128 + k];
                v.z = W_ih[(j + 512)*128 + k];
                v.w = W_ih[(j + 768)*128 + k];
            } else {
                int kk = k - 128;
                v.x = W_hh[(j      )*256 + kk];
                v.y = W_hh[(j + 256)*256 + kk];
                v.z = W_hh[(j + 512)*256 + kk];
                v.w = W_hh[(j + 768)*256 + kk];
            }
            g_Wt4[idx] = v;
        }
        for (int idx = gtid; idx < 256*128; idx += gstride) {
            int kp = idx >> 7, s = idx & 127;
            ull v = 0;
            if (s < TM1) v = pack2(W1[s*512 + 2*kp], W1[s*512 + 2*kp + 1]);
            g_W1T2[idx] = v;
        }
        for (int idx = gtid; idx < 1024; idx += gstride)
            g_bias[idx] = b_ih[idx] + b_hh[idx];
        for (int idx = gtid; idx < BB*HH; idx += gstride) {
            g_h[0][idx] = 0.0f;
            g_c[0][idx] = 0.0f;
        }
    }

    // ================= Z2 PHASE (block-local: own 4 batches) =================
    // z2T[b][s][n] = sum_t in[b,t,n]*W2[s,t] + b2[s]; no barrier needed (self-use).
    {
        float* w2t = sm;            // [t][s pad 112] : 99*112 floats
        float* b2s = sm + 11200;    // 112 floats
        for (int i = tid; i < 99*112; i += NTHR) w2t[i] = 0.0f;
        if (tid < 112) b2s[tid] = (tid < TM1) ? b2[tid] : 0.0f;
        __syncthreads();
        for (int i = tid; i < TM1*TM1; i += NTHR) {
            int s = i / TM1, t = i - s*TM1;
            w2t[t*112 + s] = W2[i];
        }
        __syncthreads();

        int n = tid & 127, sgrp = tid >> 7;
        int s4base = sgrp*7;                 // 7 float4 = 28 s per sgrp (padded)
        for (int bi = 0; bi < 4; bi++) {
            int b = b0 + bi;
            for (int i = tid; i < TM1*NF/4; i += NTHR)
                ((float4*)xsf)[i] = ((const float4*)(in + (size_t)b*TM1*NF))[i];
            __syncthreads();

            float4 acc[7];
            #pragma unroll
            for (int j = 0; j < 7; j++) acc[j] = make_float4(0.f,0.f,0.f,0.f);
            #pragma unroll 2
            for (int t = 0; t < TM1; t++) {
                float xv = xsf[t*128 + n];
                const float4* wr = (const float4*)(w2t + t*112) + s4base;
                #pragma unroll
                for (int j = 0; j < 7; j++) {
                    acc[j].x = fmaf(xv, wr[j].x, acc[j].x);
                    acc[j].y = fmaf(xv, wr[j].y, acc[j].y);
                    acc[j].z = fmaf(xv, wr[j].z, acc[j].z);
                    acc[j].w = fmaf(xv, wr[j].w, acc[j].w);
                }
            }
            #pragma unroll
            for (int j = 0; j < 7; j++) {
                int s0 = (s4base + j)*4;
                float v[4] = {acc[j].x, acc[j].y, acc[j].z, acc[j].w};
                #pragma unroll
                for (int c = 0; c < 4; c++) {
                    int s = s0 + c;
                    if (s < TM1)
                        g_z2T[((size_t)b*TM1 + s)*NF + n] = v[c] + b2s[s];
                }
            }
            __syncthreads();
        }
    }

    // all prep writes must be visible everywhere before the main loop
    globalbar();

    // ================= stage LSTM weight slice into smem (once) =================
    for (int idx = tid; idx < 192*16; idx += NTHR) {
        int kp = idx >> 4, q2 = idx & 15;
        int j  = jt*16 + q2;
        float4 w0 = g_Wt4[(2*kp  )*256 + j];
        float4 w1 = g_Wt4[(2*kp+1)*256 + j];
        wsmu[(0*192 + kp)*16 + q2] = pack2(w0.x, w1.x);
        wsmu[(1*192 + kp)*16 + q2] = pack2(w0.y, w1.y);
        wsmu[(2*192 + kp)*16 + q2] = pack2(w0.z, w1.z);
        wsmu[(3*192 + kp)*16 + q2] = pack2(w0.w, w1.w);
    }
    for (int i = tid; i < 128; i += NTHR) {
        w3s[i] = (i < TM1) ? W3[i] : 0.0f;
        b1s[i] = (i < TM1) ? b1[i] : 0.0f;
    }
    float b3v = b3[0];

    // GEMM mapping: q = hidden unit, bg = 8-batch group, kq4 = k-quarter
    int q = tid & 15, bg = (tid >> 4) & 7, kq4 = tid >> 7;
    int jj = jt*16 + q;
    float bI = g_bias[jj], bF = g_bias[256+jj], bG = g_bias[512+jj], bO = g_bias[768+jj];
    float creg[8] = {0.f,0.f,0.f,0.f,0.f,0.f,0.f,0.f};   // live in kq4==0 threads

    // attention per-thread ids
    int sA  = tid & 127, kq = tid >> 7;      // stage-1: s-lane, k-quarter
    int biB = tid >> 7,  nB = tid & 127;     // stage-2: (bi, n) one per thread
    __syncthreads();

    for (int t = 0; t < TM1; t++) {
        const float* hsrc = g_h[t & 1];
        const float* csrc = g_c[t & 1];

        // ============ ATTENTION (batches b0..b0+3) ============
        {
            {
                int bi = tid >> 7, j4 = tid & 127;
                float4 v = (j4 < 64)
                    ? ((const float4*)(hsrc + (b0+bi)*HH))[j4]
                    : ((const float4*)(csrc + (b0+bi)*HH))[j4-64];
                ((float4*)hc)[tid] = v;
            }
            __syncthreads();

            // stage 1: per-thread partial dot over k-quarter, FFMA2
            {
                const ull* wp  = g_W1T2 + (size_t)(kq*64)*128 + sA;
                const ull* hcu = (const ull*)hc;
                ull a0=0, a1=0, a2=0, a3=0;
                int kbase = kq*64;
                #pragma unroll 4
                for (int kk = 0; kk < 64; kk++) {
                    ull wv = wp[kk*128];
                    ull h0 = hcu[0*256 + kbase + kk];
                    ull h1 = hcu[1*256 + kbase + kk];
                    ull h2 = hcu[2*256 + kbase + kk];
                    ull h3 = hcu[3*256 + kbase + kk];
                    FFMA2(a0, wv, h0); FFMA2(a1, wv, h1);
                    FFMA2(a2, wv, h2); FFMA2(a3, wv, h3);
                }
                float* z1p = xsf;            // [kq][bi][128] partials
                float2 p;
                p = unpack2(a0); z1p[(kq*4+0)*128 + sA] = p.x + p.y;
                p = unpack2(a1); z1p[(kq*4+1)*128 + sA] = p.x + p.y;
                p = unpack2(a2); z1p[(kq*4+2)*128 + sA] = p.x + p.y;
                p = unpack2(a3); z1p[(kq*4+3)*128 + sA] = p.x + p.y;
            }
            __syncthreads();
            {
                const float* z1p = xsf;
                int bi = tid >> 7, ss = tid & 127;
                float z = z1p[(0*4+bi)*128+ss] + z1p[(1*4+bi)*128+ss]
                        + z1p[(2*4+bi)*128+ss] + z1p[(3*4+bi)*128+ss];
                z1s[bi*128 + ss] = z + b1s[ss];
            }
            __syncthreads();

            // stage 2: one (bi, n) per thread; coalesced z2T, no shuffles
            {
                const float* zrow = g_z2T + (size_t)(b0+biB)*TM1*NF + nB;
                const float* z1r  = z1s + biB*128;
                float acc = 0.0f;
                #pragma unroll 3
                for (int s = 0; s < TM1; s++)
                    acc = fmaf(w3s[s], tanha(z1r[s] + zrow[(size_t)s*NF]), acc);
                es[biB*128 + nB] = acc + b3v;
            }
            __syncthreads();

            // softmax over n, write w = attn * x_t
            if (wrp < 4) {
                int bi = wrp, b = b0 + bi;
                float v0 = es[bi*128 + l],      v1 = es[bi*128 + 32 + l];
                float v2 = es[bi*128 + 64 + l], v3 = es[bi*128 + 96 + l];
                float m = wmax(fmaxf(fmaxf(v0, v1), fmaxf(v2, v3)));
                float e0 = ex2f((v0 - m) * 1.4426950408889634f);
                float e1 = ex2f((v1 - m) * 1.4426950408889634f);
                float e2 = ex2f((v2 - m) * 1.4426950408889634f);
                float e3 = ex2f((v3 - m) * 1.4426950408889634f);
                float r = rcpf(wsum(e0 + e1 + e2 + e3));
                const float* xrow = in  + (size_t)b*TM1*NF + t*NF;
                float*       orow = out + (size_t)b*TM1*NF + t*NF;
                orow[l     ] = e0 * r * xrow[l     ];
                orow[l + 32] = e1 * r * xrow[l + 32];
                orow[l + 64] = e2 * r * xrow[l + 64];
                orow[l + 96] = e3 * r * xrow[l + 96];
            }
        }
        groupbar(grp, ++bar);   // w(t) visible within group; h/c reads done

        // ============ LSTM GEMM + cell (64 batches x 16 j, k in quarters) ====
        {
            // stage x: float4 loads (w from out, h from hsrc); row stride 388
            for (int i = tid; i < 64*96; i += NTHR) {
                int bb = i / 96, k4 = i - bb*96;
                int b  = bt*64 + bb;
                float4 v = (k4 < 32)
                    ? *(const float4*)(out + (size_t)b*TM1*NF + t*NF + k4*4)
                    : *(const float4*)(hsrc + b*HH + (k4-32)*4);
                *(float4*)&xsf[bb*388 + k4*4] = v;
            }
            __syncthreads();

            ull acc0[8], acc1[8], acc2[8], acc3[8];
            #pragma unroll
            for (int m = 0; m < 8; m++) { acc0[m]=0; acc1[m]=0; acc2[m]=0; acc3[m]=0; }

            const ull* wq = wsmu + q;
            const ulonglong2* xrow = (const ulonglong2*)xsf;  // row stride 97
            int pbase = kq4*24;
            #pragma unroll 3
            for (int p = 0; p < 24; p++) {
                int kp = kq4*48 + 2*p;
                ull wI0 = wq[(0*192+kp)*16], wI1 = wq[(0*192+kp+1)*16];
                ull wF0 = wq[(1*192+kp)*16], wF1 = wq[(1*192+kp+1)*16];
                ull wG0 = wq[(2*192+kp)*16], wG1 = wq[(2*192+kp+1)*16];
                ull wO0 = wq[(3*192+kp)*16], wO1 = wq[(3*192+kp+1)*16];
                #pragma unroll
                for (int m = 0; m < 8; m++) {
                    ulonglong2 xv = xrow[(bg*8+m)*97 + pbase + p];
                    FFMA2(acc0[m], wI0, xv.x); FFMA2(acc0[m], wI1, xv.y);
                    FFMA2(acc1[m], wF0, xv.x); FFMA2(acc1[m], wF1, xv.y);
                    FFMA2(acc2[m], wG0, xv.x); FFMA2(acc2[m], wG1, xv.y);
                    FFMA2(acc3[m], wO0, xv.x); FFMA2(acc3[m], wO1, xv.y);
                }
            }

            // combine 4 k-quarters via smem scratch (stride 97 -> conflict-free)
            __syncthreads();
            ull* scratch = (ull*)xsf;
            int combo = bg*16 + q;           // 0..127
            if (kq4 > 0) {
                ull* d = scratch + (size_t)combo*97 + (kq4-1)*32;
                #pragma unroll
                for (int m = 0; m < 8; m++) {
                    d[m]    = acc0[m];
                    d[8+m]  = acc1[m];
                    d[16+m] = acc2[m];
                    d[24+m] = acc3[m];
                }
            }
            __syncthreads();

            if (kq4 == 0) {
                const ull* d = scratch + (size_t)combo*97;
                float* cdst = g_c[(t + 1) & 1];
                float* hdst = g_h[(t + 1) & 1];
                #pragma unroll
                for (int m = 0; m < 8; m++) {
                    float2 p0 = unpack2(acc0[m]), p1 = unpack2(acc1[m]);
                    float2 p2 = unpack2(acc2[m]), p3 = unpack2(acc3[m]);
                    float gi = p0.x + p0.y, gf = p1.x + p1.y;
                    float gg = p2.x + p2.y, go = p3.x + p3.y;
                    #pragma unroll
                    for (int kk = 0; kk < 3; kk++) {
                        float2 rI = unpack2(d[kk*32 + m]);
                        float2 rF = unpack2(d[kk*32 + 8 + m]);
                        float2 rG = unpack2(d[kk*32 + 16 + m]);
                        float2 rO = unpack2(d[kk*32 + 24 + m]);
                        gi += rI.x + rI.y; gf += rF.x + rF.y;
                        gg += rG.x + rG.y; go += rO.x + rO.y;
                    }
                    gi += bI; gf += bF; gg += bG; go += bO;
                    float iv = sigm_f(gi);
                    float fv = sigm_f(gf);
                    float gv = tanh_f(gg);
                    float ov = sigm_f(go);
                    float cn = fmaf(fv, creg[m], iv * gv);
                    creg[m] = cn;
                    float hn = ov * tanh_f(cn);
                    int b = bt*64 + bg*8 + m;
                    cdst[b*HH + jj] = cn;
                    hdst[b*HH + jj] = hn;
                    out[WOFF + (size_t)b*TM1*HH + t*HH + jj] = hn;
                }
            }
        }
        groupbar(grp, ++bar);   // h/c(t+1) visible within group
    }
}

// ---------------- launch ----------------
extern "C" void kernel_launch(void* const* d_in, const int* in_sizes, int n_in,
                              void* d_out, int out_size)
{
    const float* in   = (const float*)d_in[0];
    const float* W1   = (const float*)d_in[1];
    const float* b1   = (const float*)d_in[2];
    const float* W2   = (const float*)d_in[3];
    const float* b2   = (const float*)d_in[4];
    const float* W3   = (const float*)d_in[5];
    const float* b3   = (const float*)d_in[6];
    const float* W_ih = (const float*)d_in[7];
    const float* W_hh = (const float*)d_in[8];
    const float* b_ih = (const float*)d_in[9];
    const float* b_hh = (const float*)d_in[10];
    float* out = (float*)d_out;

    cudaFuncSetAttribute(persist_kernel, cudaFuncAttributeMaxDynamicSharedMemorySize, SMEM_PERSIST);

    persist_kernel<<<NBLK, NTHR, SMEM_PERSIST>>>(in, W1, b1, W2, b2, W3, b3,
                                                 W_ih, W_hh, b_ih, b_hh, out);
}

// round 16
// speedup vs baseline: 1.2784x; 1.2784x over previous
#include <cuda_runtime.h>

#define BB   512
#define TM1  99
#define NF   128
#define HH   256
#define WOFF (BB*TM1*NF)
#define NBLK 128
#define NTHR 512
#define NGRP 8                 // 8 independent groups of 16 CTAs

typedef unsigned long long ull;

// ---------------- device scratch ----------------
__device__ float  g_z2T[(size_t)BB*TM1*NF]; // transposed: [b][s][n]
__device__ float  g_h[2][BB*HH];
__device__ float  g_c[2][BB*HH];
__device__ float4 g_Wt4[384*256];         // [k][j] -> (Wi,Wf,Wg,Wo)
__device__ ull    g_W1T2[256*128];        // [kp][s] -> (W1[s][2kp], W1[s][2kp+1]), s pad 128
__device__ float  g_W2t[TM1*100];         // W2 transposed [t][s], s pad 100
__device__ float  g_bias[1024];

// group barrier state: each counter/release on its own 128B line
struct __align__(128) PadU { unsigned v; unsigned pad[31]; };
__device__ PadU g_cnt[NGRP];
__device__ PadU g_rel[NGRP];

// ---------------- math helpers ----------------
__device__ __forceinline__ float ex2f(float x){ float y; asm("ex2.approx.f32 %0, %1;" : "=f"(y) : "f"(x)); return y; }
__device__ __forceinline__ float rcpf(float x){ float y; asm("rcp.approx.f32 %0, %1;" : "=f"(y) : "f"(x)); return y; }
__device__ __forceinline__ float tanha(float x){ float y; asm("tanh.approx.f32 %0, %1;" : "=f"(y) : "f"(x)); return y; }
__device__ __forceinline__ float tanh_f(float x){
    float a  = fabsf(x);
    float em = ex2f(a * -2.8853900817779268f);
    float r  = (1.0f - em) * rcpf(1.0f + em);
    return copysignf(r, x);
}
__device__ __forceinline__ float sigm_f(float x){
    float e = ex2f(x * -1.4426950408889634f);
    return rcpf(1.0f + e);
}
__device__ __forceinline__ float wsum(float v){
    #pragma unroll
    for (int o = 16; o; o >>= 1) v += __shfl_xor_sync(0xffffffffu, v, o);
    return v;
}
__device__ __forceinline__ float wmax(float v){
    #pragma unroll
    for (int o = 16; o; o >>= 1) v = fmaxf(v, __shfl_xor_sync(0xffffffffu, v, o));
    return v;
}
__device__ __forceinline__ ull pack2(float a, float b){ ull r; asm("mov.b64 %0, {%1,%2};" : "=l"(r) : "f"(a), "f"(b)); return r; }
__device__ __forceinline__ float2 unpack2(ull v){ float2 r; asm("mov.b64 {%0,%1}, %2;" : "=f"(r.x), "=f"(r.y) : "l"(v)); return r; }
#define FFMA2(d,a,b) asm("fma.rn.f32x2 %0, %1, %2, %0;" : "+l"(d) : "l"(a), "l"(b))

// ---------------- group-local barrier (16 CTAs per group) ----------------
__device__ __forceinline__ void groupbar(int g, unsigned e){
    __threadfence();                         // release
    __syncthreads();
    if (threadIdx.x == 0) {
        unsigned old = atomicAdd(&g_cnt[g].v, 1u);
        if ((old & 15u) == 15u) {
            *((volatile unsigned*)&g_rel[g].v) = e;
        } else {
            while (*((volatile unsigned*)&g_rel[g].v) < e) { }
        }
        __threadfence();                     // acquire + drop stale L1 lines
    }
    __syncthreads();
}

// ---------------- prep ----------------
__global__ void prep_kernel(const float* __restrict__ W_ih, const float* __restrict__ W_hh,
                            const float* __restrict__ b_ih, const float* __restrict__ b_hh,
                            const float* __restrict__ W2,   const float* __restrict__ W1)
{
    int stride = gridDim.x * blockDim.x;
    int tid0   = blockIdx.x * blockDim.x + threadIdx.x;

    for (int idx = tid0; idx < 384*256; idx += stride) {
        int k = idx >> 8, j = idx & 255;
        float4 v;
        if (k < 128) {
            v.x = W_ih[(j      )*128 + k];
            v.y = W_ih[(j + 256)*128 + k];
            v.z = W_ih[(j + 512)*128 + k];
            v.w = W_ih[(j + 768)*128 + k];
        } else {
            int kk = k - 128;
            v.x = W_hh[(j      )*256 + kk];
            v.y = W_hh[(j + 256)*256 + kk];
            v.z = W_hh[(j + 512)*256 + kk];
            v.w = W_hh[(j + 768)*256 + kk];
        }
        g_Wt4[idx] = v;
    }
    // W1 transposed + k-paired: [kp][s]
    for (int idx = tid0; idx < 256*128; idx += stride) {
        int kp = idx >> 7, s = idx & 127;
        ull v = 0;
        if (s < TM1) v = pack2(W1[s*512 + 2*kp], W1[s*512 + 2*kp + 1]);
        g_W1T2[idx] = v;
    }
    for (int idx = tid0; idx < TM1*100; idx += stride) {
        int t = idx / 100, s = idx - t*100;
        g_W2t[idx] = (s < TM1) ? W2[s*TM1 + t] : 0.0f;
    }
    for (int idx = tid0; idx < 1024; idx += stride)
        g_bias[idx] = b_ih[idx] + b_hh[idx];
    for (int idx = tid0; idx < BB*HH; idx += stride) {
        g_h[0][idx] = 0.0f;
        g_c[0][idx] = 0.0f;
    }
    if (blockIdx.x == 0 && threadIdx.x < NGRP) {
        g_cnt[threadIdx.x].v = 0;
        g_rel[threadIdx.x].v = 0;
    }
}

// ---------------- z2 precompute (store transposed [b][s][n]) ----------------
__global__ void z2_kernel(const float* __restrict__ in, const float* __restrict__ b2)
{
    __shared__ float inT[64*TM1];
    int b  = blockIdx.x >> 1;
    int nh = blockIdx.x & 1;
    int tid = threadIdx.x;

    for (int i = tid; i < 64*TM1; i += 256) {
        int t = i >> 6, nn = i & 63;
        inT[nn*TM1 + t] = in[b*TM1*NF + t*NF + nh*64 + nn];
    }
    __syncthreads();

    int w = tid >> 5, l = tid & 31;
    if (l < 25) {
        int s0 = 4*l;
        float4 bb;
        bb.x = (s0+0 < TM1) ? b2[s0+0] : 0.0f;
        bb.y = (s0+1 < TM1) ? b2[s0+1] : 0.0f;
        bb.z = (s0+2 < TM1) ? b2[s0+2] : 0.0f;
        bb.w = (s0+3 < TM1) ? b2[s0+3] : 0.0f;
        const float4* wrow = (const float4*)g_W2t;   // [t][25 float4]
        for (int nn = w*8; nn < w*8 + 8; nn++) {
            float4 acc = make_float4(0.f,0.f,0.f,0.f);
            #pragma unroll 3
            for (int t = 0; t < TM1; t++) {
                float  xv = inT[nn*TM1 + t];
                float4 wv = wrow[t*25 + l];
                acc.x = fmaf(xv, wv.x, acc.x);
                acc.y = fmaf(xv, wv.y, acc.y);
                acc.z = fmaf(xv, wv.z, acc.z);
                acc.w = fmaf(xv, wv.w, acc.w);
            }
            acc.x += bb.x; acc.y += bb.y; acc.z += bb.z; acc.w += bb.w;
            int n = nh*64 + nn;
            size_t base = ((size_t)b*TM1 + s0)*NF + n;
            g_z2T[base] = acc.x;
            if (s0+1 < TM1) g_z2T[base +   NF] = acc.y;
            if (s0+2 < TM1) g_z2T[base + 2*NF] = acc.z;
            if (s0+3 < TM1) g_z2T[base + 3*NF] = acc.w;
        }
    }
}

// ---------------- persistent fused kernel ----------------
// grid = 128 x 512. block = (grp = bid>>4, u = bid&15).
// attention: batches grp*64+u*4..+4.  LSTM: j-tile u, batches grp*64..+64.
// dyn smem (floats): wsmu 24576 | xsf 24832 | hc 2048 | z1p 2048 |
//                    z1s 512 | es 512 | w3s 128 | b1s 128   = 54784 f = 219136 B
#define SMEM_PERSIST (54784*4)
__global__ __launch_bounds__(NTHR, 1) void persist_kernel(
    const float* __restrict__ in, const float* __restrict__ b1,
    const float* __restrict__ W3, const float* __restrict__ b3, float* __restrict__ out)
{
    extern __shared__ float sm[];
    ulonglong2* wsm2 = (ulonglong2*)sm;      // [gate][kp2][q] : 4*96*16 ull2 (98304 B)
    float* xsf  = sm + 24576;                // [bb][k], row stride 388 floats (97 ull2)
    float* hc   = sm + 49408;                // 4*512
    float* z1p  = sm + 51456;                // 16*128 z1 partials
    float* z1s  = sm + 53504;                // 4*128
    float* es   = sm + 54016;                // 4*128
    float* w3s  = sm + 54528;                // 128
    float* b1s  = sm + 54656;                // 128

    int bid = blockIdx.x, tid = threadIdx.x;
    int wrp = tid >> 5, l = tid & 31;
    int grp = bid >> 4, u = bid & 15;
    int jt  = u, bt = grp;
    int b0  = grp*64 + u*4;                  // attention batches

    // stage LSTM weight slice into smem once: ull2 = (pair(4kp2), pair(4kp2+2))
    for (int idx = tid; idx < 96*16; idx += NTHR) {
        int kp2 = idx >> 4, q2 = idx & 15;
        int j   = jt*16 + q2;
        float4 wa = g_Wt4[(4*kp2+0)*256 + j];
        float4 wb = g_Wt4[(4*kp2+1)*256 + j];
        float4 wc = g_Wt4[(4*kp2+2)*256 + j];
        float4 wd = g_Wt4[(4*kp2+3)*256 + j];
        wsm2[(0*96+kp2)*16+q2] = make_ulonglong2(pack2(wa.x,wb.x), pack2(wc.x,wd.x));
        wsm2[(1*96+kp2)*16+q2] = make_ulonglong2(pack2(wa.y,wb.y), pack2(wc.y,wd.y));
        wsm2[(2*96+kp2)*16+q2] = make_ulonglong2(pack2(wa.z,wb.z), pack2(wc.z,wd.z));
        wsm2[(3*96+kp2)*16+q2] = make_ulonglong2(pack2(wa.w,wb.w), pack2(wc.w,wd.w));
    }
    // step-invariant small arrays
    for (int i = tid; i < 128; i += NTHR) {
        w3s[i] = (i < TM1) ? W3[i] : 0.0f;
        b1s[i] = (i < TM1) ? b1[i] : 0.0f;
    }
    float b3v = b3[0];

    // GEMM mapping: q = hidden unit, bg = 2-batch group (0..31), full k per thread
    int q = tid & 15, bg = tid >> 4;
    int jj = jt*16 + q;
    float bI = g_bias[jj], bF = g_bias[256+jj], bG = g_bias[512+jj], bO = g_bias[768+jj];
    float creg[2] = {0.f, 0.f};

    // attention per-thread ids
    int sA  = tid & 127, kq = tid >> 7;      // stage-1: s-lane, k-quarter
    int biB = tid >> 7,  nB = tid & 127;     // stage-2: (bi, n) one per thread
    __syncthreads();

    unsigned bar = 0;
    for (int t = 0; t < TM1; t++) {
        const float* hsrc = g_h[t & 1];
        const float* csrc = g_c[t & 1];

        // prestage h(t) into xsf rows (k >= 128); overlaps attention compute.
        // Safe: previous step's GEMM reads of xsf completed at groupbar's sync.
        for (int i = tid; i < 64*64; i += NTHR) {
            int bb = i >> 6, k4 = i & 63;
            *(float4*)&xsf[bb*388 + NF + k4*4] =
                *(const float4*)(hsrc + (bt*64+bb)*HH + k4*4);
        }

        // ============ ATTENTION (batches b0..b0+3) ============
        {
            {
                int bi = tid >> 7, j4 = tid & 127;
                float4 v = (j4 < 64)
                    ? ((const float4*)(hsrc + (b0+bi)*HH))[j4]
                    : ((const float4*)(csrc + (b0+bi)*HH))[j4-64];
                ((float4*)hc)[tid] = v;
            }
            __syncthreads();

            // stage 1: per-thread partial dot over k-quarter, FFMA2
            {
                const ull* wp  = g_W1T2 + (size_t)(kq*64)*128 + sA;
                const ull* hcu = (const ull*)hc;
                ull a0=0, a1=0, a2=0, a3=0;
                int kbase = kq*64;
                #pragma unroll 4
                for (int kk = 0; kk < 64; kk++) {
                    ull wv = wp[kk*128];
                    ull h0 = hcu[0*256 + kbase + kk];
                    ull h1 = hcu[1*256 + kbase + kk];
                    ull h2 = hcu[2*256 + kbase + kk];
                    ull h3 = hcu[3*256 + kbase + kk];
                    FFMA2(a0, wv, h0); FFMA2(a1, wv, h1);
                    FFMA2(a2, wv, h2); FFMA2(a3, wv, h3);
                }
                float2 p;
                p = unpack2(a0); z1p[(kq*4+0)*128 + sA] = p.x + p.y;
                p = unpack2(a1); z1p[(kq*4+1)*128 + sA] = p.x + p.y;
                p = unpack2(a2); z1p[(kq*4+2)*128 + sA] = p.x + p.y;
                p = unpack2(a3); z1p[(kq*4+3)*128 + sA] = p.x + p.y;
            }
            __syncthreads();
            {
                int bi = tid >> 7, ss = tid & 127;
                float z = z1p[(0*4+bi)*128+ss] + z1p[(1*4+bi)*128+ss]
                        + z1p[(2*4+bi)*128+ss] + z1p[(3*4+bi)*128+ss];
                z1s[bi*128 + ss] = z + b1s[ss];
            }
            __syncthreads();

            // stage 2: one (bi, n) per thread; coalesced z2T, no shuffles
            {
                const float* zrow = g_z2T + (size_t)(b0+biB)*TM1*NF + nB;
                const float* z1r  = z1s + biB*128;
                float acc = 0.0f;
                #pragma unroll 3
                for (int s = 0; s < TM1; s++)
                    acc = fmaf(w3s[s], tanha(z1r[s] + zrow[(size_t)s*NF]), acc);
                es[biB*128 + nB] = acc + b3v;
            }
            __syncthreads();

            // softmax over n, write w = attn * x_t
            if (wrp < 4) {
                int bi = wrp, b = b0 + bi;
                float v0 = es[bi*128 + l],      v1 = es[bi*128 + 32 + l];
                float v2 = es[bi*128 + 64 + l], v3 = es[bi*128 + 96 + l];
                float m = wmax(fmaxf(fmaxf(v0, v1), fmaxf(v2, v3)));
                float e0 = ex2f((v0 - m) * 1.4426950408889634f);
                float e1 = ex2f((v1 - m) * 1.4426950408889634f);
                float e2 = ex2f((v2 - m) * 1.4426950408889634f);
                float e3 = ex2f((v3 - m) * 1.4426950408889634f);
                float r = rcpf(wsum(e0 + e1 + e2 + e3));
                const float* xrow = in  + (size_t)b*TM1*NF + t*NF;
                float*       orow = out + (size_t)b*TM1*NF + t*NF;
                orow[l     ] = e0 * r * xrow[l     ];
                orow[l + 32] = e1 * r * xrow[l + 32];
                orow[l + 64] = e2 * r * xrow[l + 64];
                orow[l + 96] = e3 * r * xrow[l + 96];
            }
        }
        groupbar(grp, ++bar);   // w(t) visible within group; h/c reads done

        // ============ LSTM GEMM + cell (64 batches x 16 j, full k/thread) ====
        {
            // stage w part of x only (h prestaged): 4 float4 per thread
            for (int i = tid; i < 64*32; i += NTHR) {
                int bb = i >> 5, k4 = i & 31;
                *(float4*)&xsf[bb*388 + k4*4] =
                    *(const float4*)(out + (size_t)(bt*64+bb)*TM1*NF + t*NF + k4*4);
            }
            __syncthreads();

            const ulonglong2* wq  = wsm2 + q;
            const ulonglong2* xr0 = (const ulonglong2*)xsf + (bg*2 + 0)*97;
            const ulonglong2* xr1 = (const ulonglong2*)xsf + (bg*2 + 1)*97;

            ull aI0=0, aI1=0, aF0=0, aF1=0, aG0=0, aG1=0, aO0=0, aO1=0;

            #pragma unroll 4
            for (int kp2 = 0; kp2 < 96; kp2++) {
                ulonglong2 wI = wq[(0*96+kp2)*16];
                ulonglong2 wF = wq[(1*96+kp2)*16];
                ulonglong2 wG = wq[(2*96+kp2)*16];
                ulonglong2 wO = wq[(3*96+kp2)*16];
                ulonglong2 xa = xr0[kp2];
                ulonglong2 xb = xr1[kp2];
                FFMA2(aI0, wI.x, xa.x); FFMA2(aI0, wI.y, xa.y);
                FFMA2(aI1, wI.x, xb.x); FFMA2(aI1, wI.y, xb.y);
                FFMA2(aF0, wF.x, xa.x); FFMA2(aF0, wF.y, xa.y);
                FFMA2(aF1, wF.x, xb.x); FFMA2(aF1, wF.y, xb.y);
                FFMA2(aG0, wG.x, xa.x); FFMA2(aG0, wG.y, xa.y);
                FFMA2(aG1, wG.x, xb.x); FFMA2(aG1, wG.y, xb.y);
                FFMA2(aO0, wO.x, xa.x); FFMA2(aO0, wO.y, xa.y);
                FFMA2(aO1, wO.x, xb.x); FFMA2(aO1, wO.y, xb.y);
            }

            float* cdst = g_c[(t + 1) & 1];
            float* hdst = g_h[(t + 1) & 1];
            #pragma unroll
            for (int m = 0; m < 2; m++) {
                float2 pI = unpack2(m ? aI1 : aI0);
                float2 pF = unpack2(m ? aF1 : aF0);
                float2 pG = unpack2(m ? aG1 : aG0);
                float2 pO = unpack2(m ? aO1 : aO0);
                float gi = pI.x + pI.y + bI;
                float gf = pF.x + pF.y + bF;
                float gg = pG.x + pG.y + bG;
                float go = pO.x + pO.y + bO;
                float iv = sigm_f(gi);
                float fv = sigm_f(gf);
                float gv = tanh_f(gg);
                float ov = sigm_f(go);
                float cn = fmaf(fv, creg[m], iv * gv);
                creg[m] = cn;
                float hn = ov * tanh_f(cn);
                int b = bt*64 + bg*2 + m;
                cdst[b*HH + jj] = cn;
                hdst[b*HH + jj] = hn;
                out[WOFF + (size_t)b*TM1*HH + t*HH + jj] = hn;
            }
        }
        groupbar(grp, ++bar);   // h/c(t+1) visible within group
    }
}

// ---------------- launch ----------------
extern "C" void kernel_launch(void* const* d_in, const int* in_sizes, int n_in,
                              void* d_out, int out_size)
{
    const float* in   = (const float*)d_in[0];
    const float* W1   = (const float*)d_in[1];
    const float* b1   = (const float*)d_in[2];
    const float* W2   = (const float*)d_in[3];
    const float* b2   = (const float*)d_in[4];
    const float* W3   = (const float*)d_in[5];
    const float* b3   = (const float*)d_in[6];
    const float* W_ih = (const float*)d_in[7];
    const float* W_hh = (const float*)d_in[8];
    const float* b_ih = (const float*)d_in[9];
    const float* b_hh = (const float*)d_in[10];
    float* out = (float*)d_out;

    cudaFuncSetAttribute(persist_kernel, cudaFuncAttributeMaxDynamicSharedMemorySize, SMEM_PERSIST);

    prep_kernel<<<148, 256>>>(W_ih, W_hh, b_ih, b_hh, W2, W1);
    z2_kernel<<<1024, 256>>>(in, b2);
    persist_kernel<<<NBLK, NTHR, SMEM_PERSIST>>>(in, b1, W3, b3, out);
}

// round 17
// speedup vs baseline: 1.5959x; 1.2484x over previous
#include <cuda_runtime.h>

#define BB   512
#define TM1  99
#define NF   128
#define HH   256
#define WOFF (BB*TM1*NF)
#define NBLK 128
#define NTHR 512
#define NGRP 8                 // 8 independent groups of 16 CTAs

typedef unsigned long long ull;

// ---------------- device scratch ----------------
__device__ float  g_z2T[(size_t)BB*TM1*NF]; // transposed: [b][s][n]
__device__ float  g_h[2][BB*HH];
__device__ float  g_c[2][BB*HH];
__device__ float4 g_Wt4[384*256];         // [k][j] -> (Wi,Wf,Wg,Wo)
__device__ ull    g_W1T2[256*128];        // [kp][s] -> (W1[s][2kp], W1[s][2kp+1]), s pad 128
__device__ float  g_W2t[TM1*100];         // W2 transposed [t][s], s pad 100
__device__ float  g_bias[1024];

// group barrier state: each counter/release on its own 128B line
struct __align__(128) PadU { unsigned v; unsigned pad[31]; };
__device__ PadU g_cnt[NGRP];
__device__ PadU g_rel[NGRP];

// ---------------- math helpers ----------------
__device__ __forceinline__ float ex2f(float x){ float y; asm("ex2.approx.f32 %0, %1;" : "=f"(y) : "f"(x)); return y; }
__device__ __forceinline__ float rcpf(float x){ float y; asm("rcp.approx.f32 %0, %1;" : "=f"(y) : "f"(x)); return y; }
__device__ __forceinline__ float tanha(float x){ float y; asm("tanh.approx.f32 %0, %1;" : "=f"(y) : "f"(x)); return y; }
__device__ __forceinline__ float tanh_f(float x){
    float a  = fabsf(x);
    float em = ex2f(a * -2.8853900817779268f);
    float r  = (1.0f - em) * rcpf(1.0f + em);
    return copysignf(r, x);
}
__device__ __forceinline__ float sigm_f(float x){
    float e = ex2f(x * -1.4426950408889634f);
    return rcpf(1.0f + e);
}
__device__ __forceinline__ float wsum(float v){
    #pragma unroll
    for (int o = 16; o; o >>= 1) v += __shfl_xor_sync(0xffffffffu, v, o);
    return v;
}
__device__ __forceinline__ float wmax(float v){
    #pragma unroll
    for (int o = 16; o; o >>= 1) v = fmaxf(v, __shfl_xor_sync(0xffffffffu, v, o));
    return v;
}
__device__ __forceinline__ ull pack2(float a, float b){ ull r; asm("mov.b64 %0, {%1,%2};" : "=l"(r) : "f"(a), "f"(b)); return r; }
__device__ __forceinline__ float2 unpack2(ull v){ float2 r; asm("mov.b64 {%0,%1}, %2;" : "=f"(r.x), "=f"(r.y) : "l"(v)); return r; }
#define FFMA2(d,a,b) asm("fma.rn.f32x2 %0, %1, %2, %0;" : "+l"(d) : "l"(a), "l"(b))

// ---------------- group-local barrier (16 CTAs per group) ----------------
__device__ __forceinline__ void groupbar(int g, unsigned e){
    __threadfence();                         // release
    __syncthreads();
    if (threadIdx.x == 0) {
        unsigned old = atomicAdd(&g_cnt[g].v, 1u);
        if ((old & 15u) == 15u) {
            *((volatile unsigned*)&g_rel[g].v) = e;
        } else {
            while (*((volatile unsigned*)&g_rel[g].v) < e) { }
        }
        __threadfence();                     // acquire + drop stale L1 lines
    }
    __syncthreads();
}

// ---------------- prep ----------------
__global__ void prep_kernel(const float* __restrict__ W_ih, const float* __restrict__ W_hh,
                            const float* __restrict__ b_ih, const float* __restrict__ b_hh,
                            const float* __restrict__ W2,   const float* __restrict__ W1)
{
    int stride = gridDim.x * blockDim.x;
    int tid0   = blockIdx.x * blockDim.x + threadIdx.x;

    for (int idx = tid0; idx < 384*256; idx += stride) {
        int k = idx >> 8, j = idx & 255;
        float4 v;
        if (k < 128) {
            v.x = W_ih[(j      )*128 + k];
            v.y = W_ih[(j + 256)*128 + k];
            v.z = W_ih[(j + 512)*128 + k];
            v.w = W_ih[(j + 768)*128 + k];
        } else {
            int kk = k - 128;
            v.x = W_hh[(j      )*256 + kk];
            v.y = W_hh[(j + 256)*256 + kk];
            v.z = W_hh[(j + 512)*256 + kk];
            v.w = W_hh[(j + 768)*256 + kk];
        }
        g_Wt4[idx] = v;
    }
    // W1 transposed + k-paired: [kp][s]
    for (int idx = tid0; idx < 256*128; idx += stride) {
        int kp = idx >> 7, s = idx & 127;
        ull v = 0;
        if (s < TM1) v = pack2(W1[s*512 + 2*kp], W1[s*512 + 2*kp + 1]);
        g_W1T2[idx] = v;
    }
    for (int idx = tid0; idx < TM1*100; idx += stride) {
        int t = idx / 100, s = idx - t*100;
        g_W2t[idx] = (s < TM1) ? W2[s*TM1 + t] : 0.0f;
    }
    for (int idx = tid0; idx < 1024; idx += stride)
        g_bias[idx] = b_ih[idx] + b_hh[idx];
    for (int idx = tid0; idx < BB*HH; idx += stride) {
        g_h[0][idx] = 0.0f;
        g_c[0][idx] = 0.0f;
    }
    if (blockIdx.x == 0 && threadIdx.x < NGRP) {
        g_cnt[threadIdx.x].v = 0;
        g_rel[threadIdx.x].v = 0;
    }
}

// ---------------- z2 precompute (store transposed [b][s][n]) ----------------
__global__ void z2_kernel(const float* __restrict__ in, const float* __restrict__ b2)
{
    __shared__ float inT[64*TM1];
    int b  = blockIdx.x >> 1;
    int nh = blockIdx.x & 1;
    int tid = threadIdx.x;

    for (int i = tid; i < 64*TM1; i += 256) {
        int t = i >> 6, nn = i & 63;
        inT[nn*TM1 + t] = in[b*TM1*NF + t*NF + nh*64 + nn];
    }
    __syncthreads();

    int w = tid >> 5, l = tid & 31;
    if (l < 25) {
        int s0 = 4*l;
        float4 bb;
        bb.x = (s0+0 < TM1) ? b2[s0+0] : 0.0f;
        bb.y = (s0+1 < TM1) ? b2[s0+1] : 0.0f;
        bb.z = (s0+2 < TM1) ? b2[s0+2] : 0.0f;
        bb.w = (s0+3 < TM1) ? b2[s0+3] : 0.0f;
        const float4* wrow = (const float4*)g_W2t;   // [t][25 float4]
        for (int nn = w*8; nn < w*8 + 8; nn++) {
            float4 acc = make_float4(0.f,0.f,0.f,0.f);
            #pragma unroll 3
            for (int t = 0; t < TM1; t++) {
                float  xv = inT[nn*TM1 + t];
                float4 wv = wrow[t*25 + l];
                acc.x = fmaf(xv, wv.x, acc.x);
                acc.y = fmaf(xv, wv.y, acc.y);
                acc.z = fmaf(xv, wv.z, acc.z);
                acc.w = fmaf(xv, wv.w, acc.w);
            }
            acc.x += bb.x; acc.y += bb.y; acc.z += bb.z; acc.w += bb.w;
            int n = nh*64 + nn;
            size_t base = ((size_t)b*TM1 + s0)*NF + n;
            g_z2T[base] = acc.x;
            if (s0+1 < TM1) g_z2T[base +   NF] = acc.y;
            if (s0+2 < TM1) g_z2T[base + 2*NF] = acc.z;
            if (s0+3 < TM1) g_z2T[base + 3*NF] = acc.w;
        }
    }
}

// ---------------- persistent fused kernel ----------------
// grid = 128 x 512. block = (grp = bid>>4, u = bid&15).
// attention: batches grp*64+u*4..+4.  LSTM: j-tile u, batches grp*64..+64.
// dyn smem (floats): wsmu 24576 | xsf 24832 (also z1p + GEMM scratch) |
//                    hc 2048 | z1s 512 | es 512 | w3s 128 | b1s 128
#define SMEM_PERSIST (52736*4)
__global__ __launch_bounds__(NTHR, 1) void persist_kernel(
    const float* __restrict__ in, const float* __restrict__ b1,
    const float* __restrict__ W3, const float* __restrict__ b3, float* __restrict__ out)
{
    extern __shared__ float sm[];
    ull*   wsmu = (ull*)sm;                  // [gate][kp][q]
    float* xsf  = sm + 24576;                // [bb][k], row stride 388 (float4-aligned)
    float* hc   = sm + 49408;                // 4*512
    float* z1s  = sm + 51456;                // 4*128
    float* es   = sm + 51968;                // 4*128
    float* w3s  = sm + 52480;                // 128
    float* b1s  = sm + 52608;                // 128

    int bid = blockIdx.x, tid = threadIdx.x;
    int wrp = tid >> 5, l = tid & 31;
    int grp = bid >> 4, u = bid & 15;
    int jt  = u, bt = grp;
    int b0  = grp*64 + u*4;                  // attention batches

    // stage LSTM weight slice into smem once (k-paired per gate)
    for (int idx = tid; idx < 192*16; idx += NTHR) {
        int kp = idx >> 4, q2 = idx & 15;
        int j  = jt*16 + q2;
        float4 w0 = g_Wt4[(2*kp  )*256 + j];
        float4 w1 = g_Wt4[(2*kp+1)*256 + j];
        wsmu[(0*192 + kp)*16 + q2] = pack2(w0.x, w1.x);
        wsmu[(1*192 + kp)*16 + q2] = pack2(w0.y, w1.y);
        wsmu[(2*192 + kp)*16 + q2] = pack2(w0.z, w1.z);
        wsmu[(3*192 + kp)*16 + q2] = pack2(w0.w, w1.w);
    }
    // step-invariant small arrays
    for (int i = tid; i < 128; i += NTHR) {
        w3s[i] = (i < TM1) ? W3[i] : 0.0f;
        b1s[i] = (i < TM1) ? b1[i] : 0.0f;
    }
    float b3v = b3[0];

    // GEMM mapping: q = hidden unit, bg = 4-batch group, kh = k-half
    int q  = tid & 15, bg = (tid >> 4) & 15, kh = tid >> 8;
    int jj = jt*16 + q;
    float bI = g_bias[jj], bF = g_bias[256+jj], bG = g_bias[512+jj], bO = g_bias[768+jj];
    float creg[4] = {0.f, 0.f, 0.f, 0.f};    // live in kh==0 threads

    // attention per-thread ids
    int sA  = tid & 127, kq = tid >> 7;      // stage-1: s-lane, k-quarter
    int biB = tid >> 7,  nB = tid & 127;     // stage-2: (bi, n) one per thread
    __syncthreads();

    unsigned bar = 0;
    for (int t = 0; t < TM1; t++) {
        const float* hsrc = g_h[t & 1];
        const float* csrc = g_c[t & 1];

        // ============ ATTENTION (batches b0..b0+3) ============
        {
            // stage hc: 1 float4 per thread
            {
                int bi = tid >> 7, j4 = tid & 127;
                float4 v = (j4 < 64)
                    ? ((const float4*)(hsrc + (b0+bi)*HH))[j4]
                    : ((const float4*)(csrc + (b0+bi)*HH))[j4-64];
                ((float4*)hc)[tid] = v;
            }
            __syncthreads();

            // stage 1: per-thread partial dot over k-quarter, FFMA2 (MLP 8)
            {
                const ull* wp  = g_W1T2 + (size_t)(kq*64)*128 + sA;  // row stride 128 ull
                const ull* hcu = (const ull*)hc;                      // [bi][256]
                ull a0=0, a1=0, a2=0, a3=0;
                int kbase = kq*64;
                #pragma unroll 8
                for (int kk = 0; kk < 64; kk++) {
                    ull wv = wp[kk*128];
                    ull h0 = hcu[0*256 + kbase + kk];
                    ull h1 = hcu[1*256 + kbase + kk];
                    ull h2 = hcu[2*256 + kbase + kk];
                    ull h3 = hcu[3*256 + kbase + kk];
                    FFMA2(a0, wv, h0); FFMA2(a1, wv, h1);
                    FFMA2(a2, wv, h2); FFMA2(a3, wv, h3);
                }
                float* z1p = xsf;            // [kq][bi][128] partials
                float2 p;
                p = unpack2(a0); z1p[(kq*4+0)*128 + sA] = p.x + p.y;
                p = unpack2(a1); z1p[(kq*4+1)*128 + sA] = p.x + p.y;
                p = unpack2(a2); z1p[(kq*4+2)*128 + sA] = p.x + p.y;
                p = unpack2(a3); z1p[(kq*4+3)*128 + sA] = p.x + p.y;
            }
            __syncthreads();
            {   // combine partials -> z1s
                const float* z1p = xsf;
                int bi = tid >> 7, ss = tid & 127;
                float z = z1p[(0*4+bi)*128+ss] + z1p[(1*4+bi)*128+ss]
                        + z1p[(2*4+bi)*128+ss] + z1p[(3*4+bi)*128+ss];
                z1s[bi*128 + ss] = z + b1s[ss];
            }
            __syncthreads();

            // stage 2: one (bi, n) per thread; coalesced z2T; unroll 9 for MLP
            {
                const float* zrow = g_z2T + (size_t)(b0+biB)*TM1*NF + nB;
                const float* z1r  = z1s + biB*128;
                float acc = 0.0f;
                #pragma unroll 9
                for (int s = 0; s < TM1; s++)
                    acc = fmaf(w3s[s], tanha(z1r[s] + zrow[(size_t)s*NF]), acc);
                es[biB*128 + nB] = acc + b3v;
            }
            __syncthreads();

            // softmax over n, write w = attn * x_t
            if (wrp < 4) {
                int bi = wrp, b = b0 + bi;
                float v0 = es[bi*128 + l],      v1 = es[bi*128 + 32 + l];
                float v2 = es[bi*128 + 64 + l], v3 = es[bi*128 + 96 + l];
                float m = wmax(fmaxf(fmaxf(v0, v1), fmaxf(v2, v3)));
                float e0 = ex2f((v0 - m) * 1.4426950408889634f);
                float e1 = ex2f((v1 - m) * 1.4426950408889634f);
                float e2 = ex2f((v2 - m) * 1.4426950408889634f);
                float e3 = ex2f((v3 - m) * 1.4426950408889634f);
                float r = rcpf(wsum(e0 + e1 + e2 + e3));
                const float* xrow = in  + (size_t)b*TM1*NF + t*NF;
                float*       orow = out + (size_t)b*TM1*NF + t*NF;
                orow[l     ] = e0 * r * xrow[l     ];
                orow[l + 32] = e1 * r * xrow[l + 32];
                orow[l + 64] = e2 * r * xrow[l + 64];
                orow[l + 96] = e3 * r * xrow[l + 96];
            }
        }
        groupbar(grp, ++bar);   // w(t) visible within group; h/c reads done

        // ============ LSTM GEMM + cell (64 batches x 16 j, k split in 2) ====
        {
            // stage x: float4 loads (w from out, h from hsrc)
            for (int i = tid; i < 64*96; i += NTHR) {
                int bb = i / 96, k4 = i - bb*96;
                int b  = bt*64 + bb;
                float4 v = (k4 < 32)
                    ? *(const float4*)(out + (size_t)b*TM1*NF + t*NF + k4*4)
                    : *(const float4*)(hsrc + b*HH + (k4-32)*4);
                *(float4*)&xsf[bb*388 + k4*4] = v;
            }
            __syncthreads();

            const ull* xu = (const ull*)xsf;   // row stride 194 ull
            const ull* x0 = xu + (bg*4 + 0)*194 + kh*96;
            const ull* x1 = xu + (bg*4 + 1)*194 + kh*96;
            const ull* x2 = xu + (bg*4 + 2)*194 + kh*96;
            const ull* x3 = xu + (bg*4 + 3)*194 + kh*96;
            const ull* wI = wsmu + (0*192 + kh*96)*16 + q;
            const ull* wF = wsmu + (1*192 + kh*96)*16 + q;
            const ull* wG = wsmu + (2*192 + kh*96)*16 + q;
            const ull* wO = wsmu + (3*192 + kh*96)*16 + q;

            ull aI[4] = {0,0,0,0}, aF[4] = {0,0,0,0}, aG[4] = {0,0,0,0}, aO[4] = {0,0,0,0};

            #pragma unroll 2
            for (int kp = 0; kp < 96; kp++) {
                ull vI = wI[kp*16], vF = wF[kp*16], vG = wG[kp*16], vO = wO[kp*16];
                ull xv0 = x0[kp], xv1 = x1[kp], xv2 = x2[kp], xv3 = x3[kp];
                FFMA2(aI[0], vI, xv0); FFMA2(aI[1], vI, xv1); FFMA2(aI[2], vI, xv2); FFMA2(aI[3], vI, xv3);
                FFMA2(aF[0], vF, xv0); FFMA2(aF[1], vF, xv1); FFMA2(aF[2], vF, xv2); FFMA2(aF[3], vF, xv3);
                FFMA2(aG[0], vG, xv0); FFMA2(aG[1], vG, xv1); FFMA2(aG[2], vG, xv2); FFMA2(aG[3], vG, xv3);
                FFMA2(aO[0], vO, xv0); FFMA2(aO[1], vO, xv1); FFMA2(aO[2], vO, xv2); FFMA2(aO[3], vO, xv3);
            }

            // combine k-halves via smem scratch (reuse xsf region)
            __syncthreads();
            ull* scratch = (ull*)xsf;
            if (kh == 1) {
                ull* d = scratch + (size_t)(bg*16 + q)*16;
                d[0]  = aI[0]; d[1]  = aI[1]; d[2]  = aI[2]; d[3]  = aI[3];
                d[4]  = aF[0]; d[5]  = aF[1]; d[6]  = aF[2]; d[7]  = aF[3];
                d[8]  = aG[0]; d[9]  = aG[1]; d[10] = aG[2]; d[11] = aG[3];
                d[12] = aO[0]; d[13] = aO[1]; d[14] = aO[2]; d[15] = aO[3];
            }
            __syncthreads();

            if (kh == 0) {
                const ull* d = scratch + (size_t)(bg*16 + q)*16;
                float* cdst = g_c[(t + 1) & 1];
                float* hdst = g_h[(t + 1) & 1];
                #pragma unroll
                for (int m = 0; m < 4; m++) {
                    float2 pI = unpack2(aI[m]), rI = unpack2(d[m]);
                    float2 pF = unpack2(aF[m]), rF = unpack2(d[4+m]);
                    float2 pG = unpack2(aG[m]), rG = unpack2(d[8+m]);
                    float2 pO = unpack2(aO[m]), rO = unpack2(d[12+m]);
                    float gi = (pI.x + pI.y) + (rI.x + rI.y) + bI;
                    float gf = (pF.x + pF.y) + (rF.x + rF.y) + bF;
                    float gg = (pG.x + pG.y) + (rG.x + rG.y) + bG;
                    float go = (pO.x + pO.y) + (rO.x + rO.y) + bO;
                    float iv = sigm_f(gi);
                    float fv = sigm_f(gf);
                    float gv = tanh_f(gg);
                    float ov = sigm_f(go);
                    float cn = fmaf(fv, creg[m], iv * gv);
                    creg[m] = cn;
                    float hn = ov * tanh_f(cn);
                    int b = bt*64 + bg*4 + m;
                    cdst[b*HH + jj] = cn;
                    hdst[b*HH + jj] = hn;
                    out[WOFF + (size_t)b*TM1*HH + t*HH + jj] = hn;
                }
            }
        }
        groupbar(grp, ++bar);   // h/c(t+1) visible within group
    }
}

// ---------------- launch ----------------
extern "C" void kernel_launch(void* const* d_in, const int* in_sizes, int n_in,
                              void* d_out, int out_size)
{
    const float* in   = (const float*)d_in[0];
    const float* W1   = (const float*)d_in[1];
    const float* b1   = (const float*)d_in[2];
    const float* W2   = (const float*)d_in[3];
    const float* b2   = (const float*)d_in[4];
    const float* W3   = (const float*)d_in[5];
    const float* b3   = (const float*)d_in[6];
    const float* W_ih = (const float*)d_in[7];
    const float* W_hh = (const float*)d_in[8];
    const float* b_ih = (const float*)d_in[9];
    const float* b_hh = (const float*)d_in[10];
    float* out = (float*)d_out;

    cudaFuncSetAttribute(persist_kernel, cudaFuncAttributeMaxDynamicSharedMemorySize, SMEM_PERSIST);

    prep_kernel<<<148, 256>>>(W_ih, W_hh, b_ih, b_hh, W2, W1);
    z2_kernel<<<1024, 256>>>(in, b2);
    persist_kernel<<<NBLK, NTHR, SMEM_PERSIST>>>(in, b1, W3, b3, out);
}